// round 8
// baseline (speedup 1.0000x reference)
#include <cuda_runtime.h>
#include <cuda_bf16.h>

#define N_NODES    100000
#define OUTPUT_DIM 128
#define KEEP_INV   (1.0f / 0.9f)

// Static device scratch (no allocations allowed)
__device__ int g_mask_mode;              // 0 = uint8/bool, 1 = int32, 2 = float32
__device__ int g_row_start[N_NODES + 1]; // CSR row pointers

// ---------------------------------------------------------------------------
// Kernel 1 (fused): build CSR row_start from sorted COO rows AND, in block 0,
// classify the keep_mask storage dtype from byte statistics.
//
// rowptr: row_start[r] = first i with rows[i] >= r ; row_start[N] = nnz.
// detect (block 0 only, all 256 threads):
//   keep_prob = 0.9 =>
//     uint8 layout  -> ~90% of first 1024 bytes equal 0x01
//     int32 layout  -> ints==1 ~90%, bytes==1 only ~22%
//     float32 layout-> floats==1.0f ~90%, bytes==1 ~0%
// Deterministic: same input -> same result every launch.
// ---------------------------------------------------------------------------
__global__ void __launch_bounds__(256)
rowptr_and_detect_kernel(const int* __restrict__ rows,
                         const unsigned char* __restrict__ m,
                         int nnz)
{
    const int i = blockIdx.x * blockDim.x + threadIdx.x;

    // ---- CSR row pointers (thread-per-nnz) ----
    if (i < nnz) {
        const int r = rows[i];
        const int rprev = (i == 0) ? -1 : rows[i - 1];
        for (int x = rprev + 1; x <= r; ++x) g_row_start[x] = i;
        if (i == nnz - 1) {
            for (int x = r + 1; x <= N_NODES; ++x) g_row_start[x] = nnz;
        }
    }

    // ---- mask dtype detection (block 0 only) ----
    if (blockIdx.x == 0) {
        const int n = nnz < 1024 ? nnz : 1024;
        const int tid = threadIdx.x;
        const int*   mi = (const int*)m;
        const float* mf = (const float*)m;

        int u8 = 0, i32 = 0, f32 = 0;
        #pragma unroll
        for (int k = 0; k < 4; ++k) {
            int s = tid + k * 256;
            if (s < n) {
                if (m[s]  == 1)    u8++;
                if (mi[s] == 1)    i32++;
                if (mf[s] == 1.0f) f32++;
            }
        }
        #pragma unroll
        for (int off = 16; off > 0; off >>= 1) {
            u8  += __shfl_down_sync(0xffffffffu, u8,  off);
            i32 += __shfl_down_sync(0xffffffffu, i32, off);
            f32 += __shfl_down_sync(0xffffffffu, f32, off);
        }
        __shared__ int s_u8[8], s_i32[8], s_f32[8];
        const int wid = tid >> 5, lane = tid & 31;
        if (lane == 0) { s_u8[wid] = u8; s_i32[wid] = i32; s_f32[wid] = f32; }
        __syncthreads();
        if (tid == 0) {
            int tu8 = 0, ti32 = 0, tf32 = 0;
            #pragma unroll
            for (int w = 0; w < 8; ++w) { tu8 += s_u8[w]; ti32 += s_i32[w]; tf32 += s_f32[w]; }
            int mode;
            if (tu8 * 4 > n * 3)        mode = 0;   // byte mask
            else if (ti32 * 4 > n * 3)  mode = 1;   // int32 mask
            else                        mode = 2;   // float32 mask
            g_mask_mode = mode;
        }
    }
}

// ---------------------------------------------------------------------------
// Kernel 2: one warp per output row, lane l owns output columns [4l, 4l+4).
//
// R4 structure (shfl staging, no smem) + 4-way unrolled inner loop with 4
// independent accumulators. Dropped nonzeros are handled branchlessly: the
// gather is issued under a predicate (compiler emits @P LDG.128 + zero
// select), so 4 independent 512B W-row gathers are in flight per warp at
// all times -> exposed gather latency / 4.
//
// Exclusive row ownership -> plain float4 store, bias fused, no atomics.
// ---------------------------------------------------------------------------
__global__ void __launch_bounds__(256)
spmm_warp_per_row_kernel(const float* __restrict__ values,
                         const int*   __restrict__ cols,
                         const void*  __restrict__ mask,
                         const float4* __restrict__ W4,     // [INPUT_DIM][32] float4
                         const float4* __restrict__ bias4,  // [32] float4
                         float4* __restrict__ out4)         // [N_NODES][32] float4
{
    const int warp = (blockIdx.x * blockDim.x + threadIdx.x) >> 5;
    const int lane = threadIdx.x & 31;
    if (warp >= N_NODES) return;

    const int s = g_row_start[warp];
    const int e = g_row_start[warp + 1];
    const int mode = g_mask_mode;

    float4 a0 = bias4[lane];
    float4 a1 = make_float4(0.f, 0.f, 0.f, 0.f);
    float4 a2 = make_float4(0.f, 0.f, 0.f, 0.f);
    float4 a3 = make_float4(0.f, 0.f, 0.f, 0.f);

    for (int base = s; base < e; base += 32) {
        const int idx = base + lane;
        float v = 0.0f;
        int   c = 0;
        if (idx < e) {
            const float val = values[idx];
            bool keep;
            if (mode == 0)      keep = ((const unsigned char*)mask)[idx] != 0;
            else if (mode == 1) keep = ((const int*)mask)[idx] != 0;
            else                keep = ((const float*)mask)[idx] != 0.0f;
            v = keep ? val * KEEP_INV : 0.0f;
            c = cols[idx];
        }
        const int cnt = (e - base) < 32 ? (e - base) : 32;

        int k = 0;
        for (; k + 4 <= cnt; k += 4) {
            const float v0 = __shfl_sync(0xffffffffu, v, k + 0);
            const float v1 = __shfl_sync(0xffffffffu, v, k + 1);
            const float v2 = __shfl_sync(0xffffffffu, v, k + 2);
            const float v3 = __shfl_sync(0xffffffffu, v, k + 3);
            const int   c0 = __shfl_sync(0xffffffffu, c, k + 0);
            const int   c1 = __shfl_sync(0xffffffffu, c, k + 1);
            const int   c2 = __shfl_sync(0xffffffffu, c, k + 2);
            const int   c3 = __shfl_sync(0xffffffffu, c, k + 3);

            // Branchless predicated gathers: 4 independent LDG.128 in flight.
            float4 w0 = make_float4(0.f, 0.f, 0.f, 0.f);
            float4 w1 = make_float4(0.f, 0.f, 0.f, 0.f);
            float4 w2 = make_float4(0.f, 0.f, 0.f, 0.f);
            float4 w3 = make_float4(0.f, 0.f, 0.f, 0.f);
            if (v0 != 0.0f) w0 = W4[c0 * 32 + lane];
            if (v1 != 0.0f) w1 = W4[c1 * 32 + lane];
            if (v2 != 0.0f) w2 = W4[c2 * 32 + lane];
            if (v3 != 0.0f) w3 = W4[c3 * 32 + lane];

            a0.x += v0 * w0.x; a0.y += v0 * w0.y; a0.z += v0 * w0.z; a0.w += v0 * w0.w;
            a1.x += v1 * w1.x; a1.y += v1 * w1.y; a1.z += v1 * w1.z; a1.w += v1 * w1.w;
            a2.x += v2 * w2.x; a2.y += v2 * w2.y; a2.z += v2 * w2.z; a2.w += v2 * w2.w;
            a3.x += v3 * w3.x; a3.y += v3 * w3.y; a3.z += v3 * w3.z; a3.w += v3 * w3.w;
        }
        for (; k < cnt; ++k) {
            const float vk = __shfl_sync(0xffffffffu, v, k);
            const int   ck = __shfl_sync(0xffffffffu, c, k);
            if (vk != 0.0f) {
                const float4 w = W4[ck * 32 + lane];
                a0.x += vk * w.x; a0.y += vk * w.y; a0.z += vk * w.z; a0.w += vk * w.w;
            }
        }
    }

    float4 acc;
    acc.x = (a0.x + a1.x) + (a2.x + a3.x);
    acc.y = (a0.y + a1.y) + (a2.y + a3.y);
    acc.z = (a0.z + a1.z) + (a2.z + a3.z);
    acc.w = (a0.w + a1.w) + (a2.w + a3.w);
    out4[warp * 32 + lane] = acc;                // 512B coalesced per warp
}

// ---------------------------------------------------------------------------
// kernel_launch — inputs per setup_inputs() order:
//   0: values  float32 [NNZ]
//   1: rows    int32   [NNZ] (sorted)
//   2: cols    int32   [NNZ]
//   3: keep_mask (bool-ish, dtype auto-detected)
//   4: weights float32 [INPUT_DIM, 128]
//   5: bias    float32 [128]
// ---------------------------------------------------------------------------
extern "C" void kernel_launch(void* const* d_in, const int* in_sizes, int n_in,
                              void* d_out, int out_size)
{
    const float* values = (const float*)d_in[0];
    const int*   rows   = (const int*)  d_in[1];
    const int*   cols   = (const int*)  d_in[2];
    const void*  mask   =               d_in[3];
    const float4* W4    = (const float4*)d_in[4];
    const float4* bias4 = (const float4*)d_in[5];
    float4* out4        = (float4*)d_out;

    const int nnz = in_sizes[0];

    {
        int threads = 256;
        int blocks = (nnz + threads - 1) / threads;
        rowptr_and_detect_kernel<<<blocks, threads>>>(
            rows, (const unsigned char*)mask, nnz);
    }

    {
        const int warps_per_block = 8;                 // 256 threads
        int blocks = (N_NODES + warps_per_block - 1) / warps_per_block;
        spmm_warp_per_row_kernel<<<blocks, 256>>>(values, cols, mask, W4, bias4, out4);
    }
}

// round 9
// speedup vs baseline: 1.3085x; 1.3085x over previous
#include <cuda_runtime.h>
#include <cuda_bf16.h>

#define N_NODES    100000
#define OUTPUT_DIM 128
#define MAX_NNZ    2000000
#define KEEP_INV   (1.0f / 0.9f)

// Static device scratch (no allocations allowed)
__device__ int    g_row_start[N_NODES + 1]; // CSR row pointers
__device__ float2 g_packed[MAX_NNZ];        // (v*KEEP_INV or 0, col-as-float-bits)

// ---------------------------------------------------------------------------
// Kernel 1 (fused prologue): for each nnz i
//   - CSR rowptr fill from sorted rows
//   - dropout applied: packed[i] = (keep ? v/keep_prob : 0, colbits)
// Mask dtype is detected PER BLOCK from the same 256-element window (all
// blocks compute the identical answer -> deterministic, no serialized detect
// kernel, no cross-kernel dependency).
//   keep_prob = 0.9 =>
//     uint8 layout  -> ~90% of first 256 bytes equal 0x01   (mean 230, thr 192)
//     int32 layout  -> bytes==1 only ~22%                    (mean 56)
//     float32 layout-> bytes==1 ~0%
// ---------------------------------------------------------------------------
__global__ void __launch_bounds__(256)
pack_and_rowptr_kernel(const float* __restrict__ values,
                       const int*   __restrict__ rows,
                       const int*   __restrict__ cols,
                       const unsigned char* __restrict__ m,
                       int nnz)
{
    // ---- per-block mask dtype detect (identical in every block) ----
    __shared__ int s_cnt[3][8];
    __shared__ int s_mode;
    {
        const int tid  = threadIdx.x;
        const int n    = nnz < 256 ? nnz : 256;     // sample window (elements)
        const int*   mi = (const int*)m;
        const float* mf = (const float*)m;

        int u8 = 0, i32 = 0, f32 = 0;
        if (tid < n) {
            if (m[tid]  == 1)    u8++;
            if (mi[tid] == 1)    i32++;              // reads bytes [4t,4t+4) <= 1024 <= nnz
            if (mf[tid] == 1.0f) f32++;
        }
        #pragma unroll
        for (int off = 16; off > 0; off >>= 1) {
            u8  += __shfl_down_sync(0xffffffffu, u8,  off);
            i32 += __shfl_down_sync(0xffffffffu, i32, off);
            f32 += __shfl_down_sync(0xffffffffu, f32, off);
        }
        const int wid = tid >> 5, lane = tid & 31;
        if (lane == 0) { s_cnt[0][wid] = u8; s_cnt[1][wid] = i32; s_cnt[2][wid] = f32; }
        __syncthreads();
        if (tid == 0) {
            int tu8 = 0, ti32 = 0;
            #pragma unroll
            for (int w = 0; w < 8; ++w) { tu8 += s_cnt[0][w]; ti32 += s_cnt[1][w]; }
            int mode;
            if (tu8 * 4 > n * 3)       mode = 0;     // byte mask
            else if (ti32 * 4 > n * 3) mode = 1;     // int32 mask
            else                       mode = 2;     // float32 mask
            s_mode = mode;
        }
        __syncthreads();
    }
    const int mode = s_mode;

    const int i = blockIdx.x * blockDim.x + threadIdx.x;
    if (i >= nnz) return;

    // ---- CSR row pointers (thread-per-nnz) ----
    {
        const int r = rows[i];
        const int rprev = (i == 0) ? -1 : rows[i - 1];
        for (int x = rprev + 1; x <= r; ++x) g_row_start[x] = i;
        if (i == nnz - 1) {
            for (int x = r + 1; x <= N_NODES; ++x) g_row_start[x] = nnz;
        }
    }

    // ---- dropout + pack ----
    bool keep;
    if (mode == 0)      keep = m[i] != 0;
    else if (mode == 1) keep = ((const int*)m)[i] != 0;
    else                keep = ((const float*)m)[i] != 0.0f;
    const float v = keep ? values[i] * KEEP_INV : 0.0f;
    g_packed[i] = make_float2(v, __int_as_float(cols[i]));
}

// ---------------------------------------------------------------------------
// Kernel 2: one warp per output row, lane l owns output columns [4l, 4l+4).
// Per nnz: ONE warp-uniform LDG.64 of (v, colbits) — 16 nnz per 128B line,
// L1-broadcast — then a warp-uniform zero-skip branch and one coalesced
// 512B W-row gather. No shfl, no staging: minimal registers (-> high
// occupancy) and a short dependency chain ptxas pipelines on its own.
// Exclusive row ownership -> plain float4 store, bias fused, no atomics.
// ---------------------------------------------------------------------------
__global__ void __launch_bounds__(256)
spmm_warp_per_row_kernel(const float4* __restrict__ W4,     // [INPUT_DIM][32] float4
                         const float4* __restrict__ bias4,  // [32] float4
                         float4* __restrict__ out4)         // [N_NODES][32] float4
{
    const int warp = (blockIdx.x * blockDim.x + threadIdx.x) >> 5;
    const int lane = threadIdx.x & 31;
    if (warp >= N_NODES) return;

    const int s = g_row_start[warp];
    const int e = g_row_start[warp + 1];

    float4 acc = bias4[lane];

    #pragma unroll 4
    for (int k = s; k < e; ++k) {
        const float2 p = g_packed[k];                // warp-uniform broadcast
        if (p.x != 0.0f) {                           // warp-uniform skip of dropped nnz
            const float4 w = W4[__float_as_int(p.y) * 32 + lane];
            acc.x += p.x * w.x;
            acc.y += p.x * w.y;
            acc.z += p.x * w.z;
            acc.w += p.x * w.w;
        }
    }

    out4[warp * 32 + lane] = acc;                    // 512B coalesced per warp
}

// ---------------------------------------------------------------------------
// kernel_launch — inputs per setup_inputs() order:
//   0: values  float32 [NNZ]
//   1: rows    int32   [NNZ] (sorted)
//   2: cols    int32   [NNZ]
//   3: keep_mask (bool-ish, dtype auto-detected)
//   4: weights float32 [INPUT_DIM, 128]
//   5: bias    float32 [128]
// ---------------------------------------------------------------------------
extern "C" void kernel_launch(void* const* d_in, const int* in_sizes, int n_in,
                              void* d_out, int out_size)
{
    const float* values = (const float*)d_in[0];
    const int*   rows   = (const int*)  d_in[1];
    const int*   cols   = (const int*)  d_in[2];
    const void*  mask   =               d_in[3];
    const float4* W4    = (const float4*)d_in[4];
    const float4* bias4 = (const float4*)d_in[5];
    float4* out4        = (float4*)d_out;

    const int nnz = in_sizes[0];

    {
        int threads = 256;
        int blocks = (nnz + threads - 1) / threads;
        pack_and_rowptr_kernel<<<blocks, threads>>>(
            values, rows, cols, (const unsigned char*)mask, nnz);
    }

    {
        const int warps_per_block = 8;                 // 256 threads
        int blocks = (N_NODES + warps_per_block - 1) / warps_per_block;
        spmm_warp_per_row_kernel<<<blocks, 256>>>(W4, bias4, out4);
    }
}